// round 2
// baseline (speedup 1.0000x reference)
#include <cuda_runtime.h>
#include <math.h>

// ---------------- problem constants ----------------
#define DD     128          // feature dim
#define NCLS   32           // number of classes
#define CHUNK  1024         // rows per chunk / per gemm CTA
#define MAXCHUNK 1024       // supports M up to 1M rows
#define GTPB   256          // gemm threads per block
#define BATCH  8            // rows staged per smem batch
#define MAXM   (1 << 19)

// ---------------- device scratch (static: no allocations allowed) ----------------
__device__ float  g_cov[NCLS][DD][DD];          // per-class covariance accumulators (upper tiles valid)
__device__ int    g_chunk_cnt[MAXCHUNK][NCLS];  // per-chunk counts -> bases after scan
__device__ int    g_counts[NCLS];
__device__ int    g_class_start[NCLS + 1];
__device__ int    g_order[MAXM];                // class-sorted row indices
__device__ double g_logdet[NCLS + 1];           // [32] = global

// ---------------- K1: per-chunk histogram + zero cov ----------------
__global__ void k_hist(const int* __restrict__ label, int M) {
    __shared__ int cnt[NCLS];
    int tid = threadIdx.x, b = blockIdx.x;
    if (tid < NCLS) cnt[tid] = 0;
    __syncthreads();
    int base = b * CHUNK;
    int end  = min(base + CHUNK, M);
    for (int r = base + tid; r < end; r += blockDim.x)
        atomicAdd(&cnt[label[r]], 1);
    __syncthreads();
    if (tid < NCLS) g_chunk_cnt[b][tid] = cnt[tid];

    // zero covariance accumulators (grid-stride over 32*128*128 floats)
    float* cf = &g_cov[0][0][0];
    const int TOT = NCLS * DD * DD;
    for (int i = b * blockDim.x + tid; i < TOT; i += gridDim.x * blockDim.x)
        cf[i] = 0.0f;
}

// ---------------- K2: offsets (single block, 32 threads) ----------------
__global__ void k_scan(int nchunk) {
    int j = threadIdx.x;
    if (j < NCLS) {
        int tot = 0;
        for (int b = 0; b < nchunk; b++) tot += g_chunk_cnt[b][j];
        g_counts[j] = tot;
    }
    __syncthreads();
    if (j == 0) {
        int s = 0;
        for (int jj = 0; jj < NCLS; jj++) { g_class_start[jj] = s; s += g_counts[jj]; }
        g_class_start[NCLS] = s;
    }
    __syncthreads();
    if (j < NCLS) {
        int s = g_class_start[j];
        for (int b = 0; b < nchunk; b++) {
            int c = g_chunk_cnt[b][j];
            g_chunk_cnt[b][j] = s;      // becomes chunk base for this class
            s += c;
        }
    }
}

// ---------------- K3: stable class-sorted order ----------------
__global__ void k_order(const int* __restrict__ label, int M) {
    __shared__ int lbl[CHUNK];
    int tid = threadIdx.x, b = blockIdx.x;
    int base = b * CHUNK;
    int n = min(CHUNK, M - base);
    for (int i = tid; i < n; i += blockDim.x) lbl[i] = label[base + i];
    __syncthreads();
    if (tid < NCLS) {
        int pos = g_chunk_cnt[b][tid];
        for (int r = 0; r < n; r++)
            if (lbl[r] == tid) g_order[pos++] = base + r;
    }
}

// ---------------- K4: segmented A^T A (upper triangle), fp32 ----------------
__device__ __forceinline__ void accum_row(const float* __restrict__ row,
                                          int ti, int tj, float acc[8][8]) {
    float av[8], bv[8];
#pragma unroll
    for (int x = 0; x < 8; x++) { av[x] = row[ti * 8 + x]; bv[x] = row[tj * 8 + x]; }
#pragma unroll
    for (int a = 0; a < 8; a++)
#pragma unroll
        for (int b2 = 0; b2 < 8; b2++)
            acc[a][b2] += av[a] * bv[b2];
}

__device__ __forceinline__ void flush_acc(int cls, int ti, int tj, float acc[8][8]) {
#pragma unroll
    for (int a = 0; a < 8; a++)
#pragma unroll
        for (int b2 = 0; b2 < 8; b2++) {
            atomicAdd(&g_cov[cls][ti * 8 + a][tj * 8 + b2], acc[a][b2]);
            acc[a][b2] = 0.0f;
        }
}

__global__ void __launch_bounds__(GTPB, 2) k_gemm(const float* __restrict__ Z, int M) {
    __shared__ float s_rows[BATCH][DD];   // 4 KB
    __shared__ int   s_ord[BATCH];
    int tid = threadIdx.x;
    int p0 = blockIdx.x * CHUNK;
    if (p0 >= M) return;
    int pend = min(p0 + CHUNK, M);

    // map threads 0..135 to upper-triangular 8x8 tile coordinates (ti<=tj)
    int ti = -1, tj = -1;
    if (tid < 136) {
        int i = 0, rem = tid;
        while (rem >= 16 - i) { rem -= 16 - i; i++; }
        ti = i; tj = i + rem;
    }

    float acc[8][8];
#pragma unroll
    for (int a = 0; a < 8; a++)
#pragma unroll
        for (int b2 = 0; b2 < 8; b2++) acc[a][b2] = 0.0f;

    // class of first position (all threads agree)
    int cur = 0;
    while (g_class_start[cur + 1] <= p0) cur++;
    int nextb = g_class_start[cur + 1];

    for (int p = p0; p < pend; p += BATCH) {
        int nb = min(BATCH, pend - p);
        __syncthreads();                       // protect s_rows/s_ord from prior batch readers
        if (tid < nb) s_ord[tid] = g_order[p + tid];
        __syncthreads();
        for (int q = tid; q < nb * (DD / 4); q += GTPB) {
            int r = q >> 5, c4 = q & 31;
            const float4* src = (const float4*)(Z + (size_t)s_ord[r] * DD);
            ((float4*)s_rows[r])[c4] = src[c4];
        }
        __syncthreads();

        if (nb == BATCH && p + BATCH <= nextb) {
            // fast path: whole batch in current class
            if (ti >= 0) {
#pragma unroll
                for (int k = 0; k < BATCH; k++)
                    accum_row(s_rows[k], ti, tj, acc);
            }
        } else {
            // slow path: per-row, with class-boundary flushes
            for (int k = 0; k < nb; k++) {
                if (p + k >= nextb) {
                    if (ti >= 0) flush_acc(cur, ti, tj, acc);
                    cur++;
                    while (g_class_start[cur + 1] <= p + k) cur++;
                    nextb = g_class_start[cur + 1];
                }
                if (ti >= 0) accum_row(s_rows[k], ti, tj, acc);
            }
        }
    }
    if (ti >= 0) flush_acc(cur, ti, tj, acc);
}

// ---------------- K5: fp64 Cholesky logdet (33 blocks) ----------------
__global__ void k_cholesky(void) {
    extern __shared__ double sA[];            // DD x (DD+1) doubles = 132096 B
    __shared__ double s_diag[DD];
    __shared__ double s_red[DD];
    const int LDA = DD + 1;
    int j = blockIdx.x;                        // 0..31 class, 32 global
    int tid = threadIdx.x;                     // 0..127

    if (j < NCLS && g_counts[j] == 0) {
        if (tid == 0) g_logdet[j] = 0.0;
        return;
    }

    // load symmetric matrix from upper-stored cov (promote to fp64)
    if (j < NCLS) {
        for (int c = 0; c < DD; c++) {
            int lo = min(tid, c), hi = max(tid, c);
            sA[tid * LDA + c] = (double)g_cov[j][lo][hi];
        }
    } else {
        for (int c = 0; c < DD; c++) {
            int lo = min(tid, c), hi = max(tid, c);
            double s = 0.0;
            for (int jj = 0; jj < NCLS; jj++) s += (double)g_cov[jj][lo][hi];
            sA[tid * LDA + c] = s;
        }
    }
    __syncthreads();

    for (int k = 0; k < DD; k++) {
        double akk = sA[k * LDA + k];
        if (tid == k) s_diag[k] = akk;
        double inv = 1.0 / sqrt(akk);
        if (tid > k) sA[tid * LDA + k] *= inv;
        __syncthreads();
        if (tid > k) {
            double lrk = sA[tid * LDA + k];
            for (int c = k + 1; c <= tid; c++)
                sA[tid * LDA + c] -= lrk * sA[c * LDA + k];
        }
        __syncthreads();
    }

    // logdet(C) = sum_k log(akk)   (akk = L_kk^2 before scaling)
    s_red[tid] = log(s_diag[tid]);
    __syncthreads();
    for (int s = DD / 2; s > 0; s >>= 1) {
        if (tid < s) s_red[tid] += s_red[tid + s];
        __syncthreads();
    }
    if (tid == 0) g_logdet[j] = s_red[0];
}

// ---------------- K6: combine into the scalar loss ----------------
__global__ void k_finalize(float* out, int M) {
    if (threadIdx.x == 0 && blockIdx.x == 0) {
        const double eps = 0.01;
        double m = (double)M;
        double comp = 0.0;
        for (int j = 0; j < NCLS; j++) {
            int mj = g_counts[j];
            if (mj > 0) {
                double cj = (double)DD / ((double)mj * eps);
                double ld = (double)DD * log(cj) + g_logdet[j];
                comp += ld * (double)mj / (2.0 * m);
            }
        }
        double c = (double)DD / (m * eps);
        double expd = ((double)DD * log(c) + g_logdet[NCLS]) * 0.5;
        out[0] = (float)(comp - expd);
    }
}

// ---------------- launch ----------------
extern "C" void kernel_launch(void* const* d_in, const int* in_sizes, int n_in,
                              void* d_out, int out_size) {
    const float* Z     = (const float*)d_in[0];
    const int*   label = (const int*)d_in[1];
    int M = in_sizes[1];
    int nchunk = (M + CHUNK - 1) / CHUNK;

    cudaFuncSetAttribute(k_cholesky, cudaFuncAttributeMaxDynamicSharedMemorySize,
                         DD * (DD + 1) * (int)sizeof(double));

    k_hist<<<nchunk, 256>>>(label, M);
    k_scan<<<1, 32>>>(nchunk);
    k_order<<<nchunk, 256>>>(label, M);
    k_gemm<<<nchunk, GTPB>>>(Z, M);
    k_cholesky<<<NCLS + 1, DD, DD * (DD + 1) * (int)sizeof(double)>>>();
    k_finalize<<<1, 1>>>((float*)d_out, M);
}

// round 4
// speedup vs baseline: 1.3906x; 1.3906x over previous
#include <cuda_runtime.h>
#include <math.h>

// ---------------- problem constants ----------------
#define DD     128          // feature dim
#define NCLS   32           // number of classes
#define CHUNK  1024         // rows per chunk / per gemm CTA
#define MAXCHUNK 1024
#define GTPB   256          // gemm threads per block
#define BATCH  8            // rows staged per smem batch
#define MAXM   (1 << 19)

// ---------------- device scratch ----------------
__device__ float  g_cov[NCLS + 1][DD][DD];      // [32] = global sum; upper tiles valid
__device__ int    g_chunk_cnt[MAXCHUNK][NCLS];  // counts -> chunk bases after scan
__device__ int    g_counts[NCLS];
__device__ int    g_class_start[NCLS + 1];
__device__ int    g_order[MAXM];
__device__ double g_logdet[NCLS + 1];

// ---------------- K1: per-chunk histogram + zero cov (R2-proven) ----------------
__global__ void k_hist(const int* __restrict__ label, int M) {
    __shared__ int cnt[NCLS];
    int tid = threadIdx.x, b = blockIdx.x;
    if (tid < NCLS) cnt[tid] = 0;
    __syncthreads();
    int base = b * CHUNK;
    int end  = min(base + CHUNK, M);
    for (int r = base + tid; r < end; r += blockDim.x)
        atomicAdd(&cnt[label[r]], 1);
    __syncthreads();
    if (tid < NCLS) g_chunk_cnt[b][tid] = cnt[tid];

    float* cf = &g_cov[0][0][0];
    const int TOT = (NCLS + 1) * DD * DD;
    for (int i = b * blockDim.x + tid; i < TOT; i += gridDim.x * blockDim.x)
        cf[i] = 0.0f;
}

// ---------------- K2: offsets (R2-proven serial-per-class version) ----------------
__global__ void k_scan(int nchunk) {
    int j = threadIdx.x;
    if (j < NCLS) {
        int tot = 0;
        for (int b = 0; b < nchunk; b++) tot += g_chunk_cnt[b][j];
        g_counts[j] = tot;
    }
    __syncthreads();
    if (j == 0) {
        int s = 0;
        for (int jj = 0; jj < NCLS; jj++) { g_class_start[jj] = s; s += g_counts[jj]; }
        g_class_start[NCLS] = s;
    }
    __syncthreads();
    if (j < NCLS) {
        int s = g_class_start[j];
        for (int b = 0; b < nchunk; b++) {
            int c = g_chunk_cnt[b][j];
            g_chunk_cnt[b][j] = s;
            s += c;
        }
    }
}

// ---------------- K3: stable class-sorted order (R2-proven) ----------------
__global__ void k_order(const int* __restrict__ label, int M) {
    __shared__ int lbl[CHUNK];
    int tid = threadIdx.x, b = blockIdx.x;
    int base = b * CHUNK;
    int n = min(CHUNK, M - base);
    for (int i = tid; i < n; i += blockDim.x) lbl[i] = label[base + i];
    __syncthreads();
    if (tid < NCLS) {
        int pos = g_chunk_cnt[b][tid];
        for (int r = 0; r < n; r++)
            if (lbl[r] == tid) g_order[pos++] = base + r;
    }
}

// ---------------- K4: segmented A^T A (upper triangle), fp32 (R2-proven) ----------
__device__ __forceinline__ void accum_row(const float* __restrict__ row,
                                          int ti, int tj, float acc[8][8]) {
    float av[8], bv[8];
#pragma unroll
    for (int x = 0; x < 8; x++) { av[x] = row[ti * 8 + x]; bv[x] = row[tj * 8 + x]; }
#pragma unroll
    for (int a = 0; a < 8; a++)
#pragma unroll
        for (int b2 = 0; b2 < 8; b2++)
            acc[a][b2] += av[a] * bv[b2];
}

__device__ __forceinline__ void flush_acc(int cls, int ti, int tj, float acc[8][8]) {
#pragma unroll
    for (int a = 0; a < 8; a++)
#pragma unroll
        for (int b2 = 0; b2 < 8; b2++) {
            float v = acc[a][b2];
            atomicAdd(&g_cov[cls][ti * 8 + a][tj * 8 + b2], v);
            atomicAdd(&g_cov[NCLS][ti * 8 + a][tj * 8 + b2], v);
            acc[a][b2] = 0.0f;
        }
}

__global__ void __launch_bounds__(GTPB, 2) k_gemm(const float* __restrict__ Z, int M) {
    __shared__ float s_rows[BATCH][DD];   // 4 KB
    __shared__ int   s_ord[BATCH];
    int tid = threadIdx.x;
    int p0 = blockIdx.x * CHUNK;
    if (p0 >= M) return;
    int pend = min(p0 + CHUNK, M);

    int ti = -1, tj = -1;
    if (tid < 136) {
        int i = 0, rem = tid;
        while (rem >= 16 - i) { rem -= 16 - i; i++; }
        ti = i; tj = i + rem;
    }

    float acc[8][8];
#pragma unroll
    for (int a = 0; a < 8; a++)
#pragma unroll
        for (int b2 = 0; b2 < 8; b2++) acc[a][b2] = 0.0f;

    int cur = 0;
    while (g_class_start[cur + 1] <= p0) cur++;
    int nextb = g_class_start[cur + 1];

    for (int p = p0; p < pend; p += BATCH) {
        int nb = min(BATCH, pend - p);
        __syncthreads();
        if (tid < nb) s_ord[tid] = g_order[p + tid];
        __syncthreads();
        for (int q = tid; q < nb * (DD / 4); q += GTPB) {
            int r = q >> 5, c4 = q & 31;
            const float4* src = (const float4*)(Z + (size_t)s_ord[r] * DD);
            ((float4*)s_rows[r])[c4] = src[c4];
        }
        __syncthreads();

        if (nb == BATCH && p + BATCH <= nextb) {
            if (ti >= 0) {
#pragma unroll
                for (int k = 0; k < BATCH; k++)
                    accum_row(s_rows[k], ti, tj, acc);
            }
        } else {
            for (int k = 0; k < nb; k++) {
                if (p + k >= nextb) {
                    if (ti >= 0) flush_acc(cur, ti, tj, acc);
                    cur++;
                    while (g_class_start[cur + 1] <= p + k) cur++;
                    nextb = g_class_start[cur + 1];
                }
                if (ti >= 0) accum_row(s_rows[k], ti, tj, acc);
            }
        }
    }
    if (ti >= 0) flush_acc(cur, ti, tj, acc);
}

// ------- K5: fp32 Cholesky with fp64-compensated diagonal (33 blocks, 128 thr) ----
__global__ void k_cholesky(void) {
    extern __shared__ float sA[];             // DD x (DD+1) floats = 66048 B
    __shared__ float  s_col[DD];
    __shared__ double s_pivot;
    __shared__ double s_logs[DD];
    const int LDA = DD + 1;
    int j = blockIdx.x;                        // 0..31 class, 32 global
    int tid = threadIdx.x;                     // 0..127

    if (j < NCLS && g_counts[j] == 0) {
        if (tid == 0) g_logdet[j] = 0.0;
        return;
    }

    // load symmetric matrix from upper-stored cov
    const float (*C)[DD] = g_cov[j];
    for (int c = 0; c < DD; c++) {
        int lo = min(tid, c), hi = max(tid, c);
        sA[tid * LDA + c] = C[lo][hi];
    }
    // fp64 running diagonal for this thread's row
    double mydiag = (double)C[tid][tid];
    __syncthreads();

    for (int k = 0; k < DD; k++) {
        if (tid == k) {
            s_pivot = mydiag;
            s_logs[k] = log(mydiag);
        }
        __syncthreads();
        float inv = rsqrtf((float)s_pivot);
        float lrk = 0.0f;
        if (tid > k) {
            lrk = sA[tid * LDA + k] * inv;
            s_col[tid] = lrk;
            mydiag -= (double)lrk * (double)lrk;   // compensated diagonal
        }
        __syncthreads();
        if (tid > k) {
            float* rowp = &sA[tid * LDA];
            int c = k + 1;
            for (; c + 3 < tid; c += 4) {          // strictly below diagonal
                rowp[c + 0] -= lrk * s_col[c + 0];
                rowp[c + 1] -= lrk * s_col[c + 1];
                rowp[c + 2] -= lrk * s_col[c + 2];
                rowp[c + 3] -= lrk * s_col[c + 3];
            }
            for (; c < tid; c++)
                rowp[c] -= lrk * s_col[c];
        }
        __syncthreads();
    }

    // reduce sum of log pivots
    __shared__ double s_red[DD];
    s_red[tid] = s_logs[tid];
    __syncthreads();
    for (int s = DD / 2; s > 0; s >>= 1) {
        if (tid < s) s_red[tid] += s_red[tid + s];
        __syncthreads();
    }
    if (tid == 0) g_logdet[j] = s_red[0];
}

// ---------------- K6: combine (one warp) ----------------
__global__ void k_finalize(float* out, int M) {
    int lane = threadIdx.x;
    double m = (double)M;
    double term = 0.0;
    if (lane < NCLS) {
        int mj = g_counts[lane];
        if (mj > 0) {
            double cj = (double)DD / ((double)mj * 0.01);
            term = ((double)DD * log(cj) + g_logdet[lane]) * (double)mj / (2.0 * m);
        }
    }
#pragma unroll
    for (int d = 16; d > 0; d >>= 1)
        term += __shfl_down_sync(0xFFFFFFFFu, term, d);
    if (lane == 0) {
        double c = (double)DD / (m * 0.01);
        double expd = ((double)DD * log(c) + g_logdet[NCLS]) * 0.5;
        out[0] = (float)(term - expd);
    }
}

// ---------------- launch ----------------
extern "C" void kernel_launch(void* const* d_in, const int* in_sizes, int n_in,
                              void* d_out, int out_size) {
    const float* Z     = (const float*)d_in[0];
    const int*   label = (const int*)d_in[1];
    int M = in_sizes[1];
    int nchunk = (M + CHUNK - 1) / CHUNK;

    cudaFuncSetAttribute(k_cholesky, cudaFuncAttributeMaxDynamicSharedMemorySize,
                         DD * (DD + 1) * (int)sizeof(float));

    k_hist<<<nchunk, 256>>>(label, M);
    k_scan<<<1, 32>>>(nchunk);
    k_order<<<nchunk, 256>>>(label, M);
    k_gemm<<<nchunk, GTPB>>>(Z, M);
    k_cholesky<<<NCLS + 1, DD, DD * (DD + 1) * (int)sizeof(float)>>>();
    k_finalize<<<1, 32>>>((float*)d_out, M);
}

// round 6
// speedup vs baseline: 1.6863x; 1.2127x over previous
#include <cuda_runtime.h>
#include <math.h>

// ---------------- problem constants ----------------
#define DD     128          // feature dim
#define NCLS   32           // number of classes
#define OCHUNK 1024         // rows per hist/order chunk
#define GCHUNK 896          // rows per gemm CTA (multiple of BATCH)
#define MAXCHUNK 1024
#define GTPB   256          // gemm threads per block
#define BATCH  16           // rows staged per smem batch
#define MAXM   (1 << 19)

// ---------------- device scratch ----------------
__device__ float  g_cov[NCLS + 1][DD][DD];      // [32] = global sum; upper tiles valid
__device__ int    g_chunk_cnt[MAXCHUNK][NCLS];
__device__ int    g_counts[NCLS];
__device__ int    g_class_start[NCLS + 1];
__device__ int    g_order[MAXM];
__device__ double g_logdet[NCLS + 1];

// ---------------- K1: per-chunk histogram + zero cov (R4-proven) ----------------
__global__ void k_hist(const int* __restrict__ label, int M) {
    __shared__ int cnt[NCLS];
    int tid = threadIdx.x, b = blockIdx.x;
    if (tid < NCLS) cnt[tid] = 0;
    __syncthreads();
    int base = b * OCHUNK;
    int end  = min(base + OCHUNK, M);
    for (int r = base + tid; r < end; r += blockDim.x)
        atomicAdd(&cnt[label[r]], 1);
    __syncthreads();
    if (tid < NCLS) g_chunk_cnt[b][tid] = cnt[tid];

    float* cf = &g_cov[0][0][0];
    const int TOT = (NCLS + 1) * DD * DD;
    for (int i = b * blockDim.x + tid; i < TOT; i += gridDim.x * blockDim.x)
        cf[i] = 0.0f;
}

// ---------------- K2: offsets (R4-proven serial-per-class) ----------------
__global__ void k_scan(int nchunk) {
    int j = threadIdx.x;
    if (j < NCLS) {
        int tot = 0;
        for (int b = 0; b < nchunk; b++) tot += g_chunk_cnt[b][j];
        g_counts[j] = tot;
    }
    __syncthreads();
    if (j == 0) {
        int s = 0;
        for (int jj = 0; jj < NCLS; jj++) { g_class_start[jj] = s; s += g_counts[jj]; }
        g_class_start[NCLS] = s;
    }
    __syncthreads();
    if (j < NCLS) {
        int s = g_class_start[j];
        for (int b = 0; b < nchunk; b++) {
            int c = g_chunk_cnt[b][j];
            g_chunk_cnt[b][j] = s;
            s += c;
        }
    }
}

// ---------------- K3: stable class-sorted order (R4-proven) ----------------
__global__ void k_order(const int* __restrict__ label, int M) {
    __shared__ int lbl[OCHUNK];
    int tid = threadIdx.x, b = blockIdx.x;
    int base = b * OCHUNK;
    int n = min(OCHUNK, M - base);
    for (int i = tid; i < n; i += blockDim.x) lbl[i] = label[base + i];
    __syncthreads();
    if (tid < NCLS) {
        int pos = g_chunk_cnt[b][tid];
        for (int r = 0; r < n; r++)
            if (lbl[r] == tid) g_order[pos++] = base + r;
    }
}

// ---------------- K4: segmented A^T A, packed f32x2 FFMA ----------------
typedef unsigned long long u64t;

__device__ __forceinline__ void accum_row2(const float* __restrict__ row,
                                           int ti, int tj, u64t acc[8][4]) {
    float4 a0 = *(const float4*)(row + (ti << 3));
    float4 a1 = *(const float4*)(row + (ti << 3) + 4);
    float4 b0 = *(const float4*)(row + (tj << 3));
    float4 b1 = *(const float4*)(row + (tj << 3) + 4);
    u64t bp[4];
    asm("mov.b64 %0, {%1, %2};" : "=l"(bp[0]) : "f"(b0.x), "f"(b0.y));
    asm("mov.b64 %0, {%1, %2};" : "=l"(bp[1]) : "f"(b0.z), "f"(b0.w));
    asm("mov.b64 %0, {%1, %2};" : "=l"(bp[2]) : "f"(b1.x), "f"(b1.y));
    asm("mov.b64 %0, {%1, %2};" : "=l"(bp[3]) : "f"(b1.z), "f"(b1.w));
    float av[8] = {a0.x, a0.y, a0.z, a0.w, a1.x, a1.y, a1.z, a1.w};
#pragma unroll
    for (int a = 0; a < 8; a++) {
        u64t ad;
        asm("mov.b64 %0, {%1, %1};" : "=l"(ad) : "f"(av[a]));
#pragma unroll
        for (int b = 0; b < 4; b++)
            asm("fma.rn.f32x2 %0, %1, %2, %0;" : "+l"(acc[a][b]) : "l"(ad), "l"(bp[b]));
    }
}

__device__ __forceinline__ void flush_acc2(int cls, int ti, int tj, u64t acc[8][4]) {
#pragma unroll
    for (int a = 0; a < 8; a++)
#pragma unroll
        for (int b = 0; b < 4; b++) {
            float lo, hi;
            asm("mov.b64 {%0, %1}, %2;" : "=f"(lo), "=f"(hi) : "l"(acc[a][b]));
            int r = ti * 8 + a, c = tj * 8 + 2 * b;
            atomicAdd(&g_cov[cls][r][c],     lo);
            atomicAdd(&g_cov[NCLS][r][c],    lo);
            atomicAdd(&g_cov[cls][r][c + 1], hi);
            atomicAdd(&g_cov[NCLS][r][c + 1], hi);
            acc[a][b] = 0ull;
        }
}

__global__ void __launch_bounds__(GTPB, 2) k_gemm(const float* __restrict__ Z, int M) {
    __shared__ float s_rows[BATCH][DD];   // 8 KB
    int tid = threadIdx.x;
    int wid = tid >> 5, lane = tid & 31;
    int p0 = blockIdx.x * GCHUNK;
    if (p0 >= M) return;
    int pend = min(p0 + GCHUNK, M);

    // threads 0..135 -> upper-triangular 8x8 tile coords (ti<=tj)
    int ti = -1, tj = -1;
    if (tid < 136) {
        int i = 0, rem = tid;
        while (rem >= 16 - i) { rem -= 16 - i; i++; }
        ti = i; tj = i + rem;
    }

    u64t acc[8][4];
#pragma unroll
    for (int a = 0; a < 8; a++)
#pragma unroll
        for (int b = 0; b < 4; b++) acc[a][b] = 0ull;

    int cur = 0;
    while (g_class_start[cur + 1] <= p0) cur++;
    int nextb = g_class_start[cur + 1];

    // staging role: warp w stages rows 2w and 2w+1 of the batch (half-warp each)
    int srow = 2 * wid + (lane >> 4);
    int scol = lane & 15;

    for (int p = p0; p < pend; p += BATCH) {
        int nb = min(BATCH, pend - p);
        __syncthreads();                       // previous batch fully consumed
        {
            int pos = p + srow;
            if (pos < pend) {
                int row = g_order[pos];        // same addr across half-warp: broadcast
                const float4* src = (const float4*)(Z + (size_t)row * DD);
                float4* dst = (float4*)s_rows[srow];
                dst[scol]      = src[scol];
                dst[scol + 16] = src[scol + 16];
            }
        }
        __syncthreads();

        if (nb == BATCH && p + BATCH <= nextb) {
            if (ti >= 0) {
#pragma unroll
                for (int k = 0; k < BATCH; k++)
                    accum_row2(s_rows[k], ti, tj, acc);
            }
        } else {
            for (int k = 0; k < nb; k++) {
                if (p + k >= nextb) {
                    if (ti >= 0) flush_acc2(cur, ti, tj, acc);
                    cur++;
                    while (g_class_start[cur + 1] <= p + k) cur++;
                    nextb = g_class_start[cur + 1];
                }
                if (ti >= 0) accum_row2(s_rows[k], ti, tj, acc);
            }
        }
    }
    if (ti >= 0) flush_acc2(cur, ti, tj, acc);
}

// ------- K5: fp32 Cholesky with fp64-compensated diagonal (R4-proven) -------
__global__ void k_cholesky(void) {
    extern __shared__ float sA[];
    __shared__ float  s_col[DD];
    __shared__ double s_pivot;
    __shared__ double s_logs[DD];
    const int LDA = DD + 1;
    int j = blockIdx.x;
    int tid = threadIdx.x;

    if (j < NCLS && g_counts[j] == 0) {
        if (tid == 0) g_logdet[j] = 0.0;
        return;
    }
    const float (*C)[DD] = g_cov[j];
    for (int c = 0; c < DD; c++) {
        int lo = min(tid, c), hi = max(tid, c);
        sA[tid * LDA + c] = C[lo][hi];
    }
    double mydiag = (double)C[tid][tid];
    __syncthreads();

    for (int k = 0; k < DD; k++) {
        if (tid == k) { s_pivot = mydiag; s_logs[k] = log(mydiag); }
        __syncthreads();
        float inv = rsqrtf((float)s_pivot);
        float lrk = 0.0f;
        if (tid > k) {
            lrk = sA[tid * LDA + k] * inv;
            s_col[tid] = lrk;
            mydiag -= (double)lrk * (double)lrk;
        }
        __syncthreads();
        if (tid > k) {
            float* rowp = &sA[tid * LDA];
            int c = k + 1;
            for (; c + 3 < tid; c += 4) {
                rowp[c + 0] -= lrk * s_col[c + 0];
                rowp[c + 1] -= lrk * s_col[c + 1];
                rowp[c + 2] -= lrk * s_col[c + 2];
                rowp[c + 3] -= lrk * s_col[c + 3];
            }
            for (; c < tid; c++) rowp[c] -= lrk * s_col[c];
        }
        __syncthreads();
    }
    __shared__ double s_red[DD];
    s_red[tid] = s_logs[tid];
    __syncthreads();
    for (int s = DD / 2; s > 0; s >>= 1) {
        if (tid < s) s_red[tid] += s_red[tid + s];
        __syncthreads();
    }
    if (tid == 0) g_logdet[j] = s_red[0];
}

// ---------------- K6: combine (one warp, R4-proven) ----------------
__global__ void k_finalize(float* out, int M) {
    int lane = threadIdx.x;
    double m = (double)M;
    double term = 0.0;
    if (lane < NCLS) {
        int mj = g_counts[lane];
        if (mj > 0) {
            double cj = (double)DD / ((double)mj * 0.01);
            term = ((double)DD * log(cj) + g_logdet[lane]) * (double)mj / (2.0 * m);
        }
    }
#pragma unroll
    for (int d = 16; d > 0; d >>= 1)
        term += __shfl_down_sync(0xFFFFFFFFu, term, d);
    if (lane == 0) {
        double c = (double)DD / (m * 0.01);
        double expd = ((double)DD * log(c) + g_logdet[NCLS]) * 0.5;
        out[0] = (float)(term - expd);
    }
}

// ---------------- launch ----------------
extern "C" void kernel_launch(void* const* d_in, const int* in_sizes, int n_in,
                              void* d_out, int out_size) {
    const float* Z     = (const float*)d_in[0];
    const int*   label = (const int*)d_in[1];
    int M = in_sizes[1];
    int nchunk = (M + OCHUNK - 1) / OCHUNK;
    int ggrid  = (M + GCHUNK - 1) / GCHUNK;

    cudaFuncSetAttribute(k_cholesky, cudaFuncAttributeMaxDynamicSharedMemorySize,
                         DD * (DD + 1) * (int)sizeof(float));

    k_hist<<<nchunk, 256>>>(label, M);
    k_scan<<<1, 32>>>(nchunk);
    k_order<<<nchunk, 256>>>(label, M);
    k_gemm<<<ggrid, GTPB>>>(Z, M);
    k_cholesky<<<NCLS + 1, DD, DD * (DD + 1) * (int)sizeof(float)>>>();
    k_finalize<<<1, 32>>>((float*)d_out, M);
}